// round 3
// baseline (speedup 1.0000x reference)
#include <cuda_runtime.h>
#include <math.h>

#define N_NODES 20000
#define NHID 128
#define HEADS 4
#define HC (HEADS * NHID)          // 512
#define E_EDGES 320000
#define ETOT (E_EDGES + N_NODES)   // 340000
#define NLAYERS 4
#define NCLASS 40
#define NEG_SLOPE 0.2f
#define DT 1.0f
#define ALPHA 1.0f
#define GAMMA 1.0f

// d_out layout: [out (N*NCLASS)] [X_all (N*(L+1)*C)] [Y_all (N*(L+1)*C)]
#define OUT_OFF   0
#define XALL_OFF  (N_NODES * NCLASS)
#define YALL_OFF  (XALL_OFF + N_NODES * (NLAYERS + 1) * NHID)
#define LSTRIDE   ((NLAYERS + 1) * NHID)   // 640 per node in X_all/Y_all

// ------------------------- device scratch (no allocs allowed) ----------------
__device__ float g_h[N_NODES * HC];          // 41 MB
__device__ float g_X[N_NODES * NHID];
__device__ float g_Y[N_NODES * NHID];
__device__ float g_as[N_NODES * HEADS];
__device__ float g_ad[N_NODES * HEADS];
__device__ float g_ex[ETOT * HEADS];         // per-CSR-position edge values
__device__ float g_den[N_NODES * HEADS];
__device__ int   g_deg[N_NODES];
__device__ int   g_cursor[N_NODES];
__device__ int   g_off[N_NODES + 1];
__device__ int   g_csr_src[ETOT];

// ------------------------- setup kernels -------------------------------------
__global__ void k_zero_int2(int* a, int* b, int n) {
    int i = blockIdx.x * blockDim.x + threadIdx.x;
    if (i < n) { a[i] = 0; b[i] = 0; }
}

__global__ void k_count_deg(const int* __restrict__ dst) {
    int e = blockIdx.x * blockDim.x + threadIdx.x;
    if (e >= ETOT) return;
    int d = (e < E_EDGES) ? dst[e] : (e - E_EDGES);
    atomicAdd(&g_deg[d], 1);
}

// single-block exclusive scan over g_deg -> g_off (N=20000)
__global__ void k_scan() {
    __shared__ int s[1024];
    const int CH = (N_NODES + 1023) / 1024;  // 20
    int tid = threadIdx.x;
    int base = tid * CH;
    int sum = 0;
    for (int i = 0; i < CH; i++) {
        int idx = base + i;
        if (idx < N_NODES) sum += g_deg[idx];
    }
    s[tid] = sum;
    __syncthreads();
    for (int d = 1; d < 1024; d <<= 1) {
        int v = (tid >= d) ? s[tid - d] : 0;
        __syncthreads();
        s[tid] += v;
        __syncthreads();
    }
    int run = (tid == 0) ? 0 : s[tid - 1];
    for (int i = 0; i < CH; i++) {
        int idx = base + i;
        if (idx < N_NODES) { g_off[idx] = run; run += g_deg[idx]; }
    }
    if (tid == 1023) g_off[N_NODES] = run;
}

__global__ void k_scatter(const int* __restrict__ src, const int* __restrict__ dst) {
    int e = blockIdx.x * blockDim.x + threadIdx.x;
    if (e >= ETOT) return;
    int d, s;
    if (e < E_EDGES) { d = dst[e]; s = src[e]; }
    else { d = e - E_EDGES; s = d; }
    int pos = g_off[d] + atomicAdd(&g_cursor[d], 1);
    g_csr_src[pos] = s;
}

// init state + write layer-0 slices of X_all / Y_all
__global__ void k_init(const float* __restrict__ x, float* __restrict__ out) {
    int n = blockIdx.x;
    int t = threadIdx.x;
    float v = x[n * NHID + t];
    g_X[n * NHID + t] = v;
    g_Y[n * NHID + t] = v;
    out[XALL_OFF + n * LSTRIDE + t] = v;
    out[YALL_OFF + n * LSTRIDE + t] = v;
}

// ------------------------- FFMA GEMM, full-K resident: h = X @ W --------------
// C[20000 x 512] = X[20000 x 128] @ W[128 x 512], row-major fp32.
// Block tile 128x128, K=128 fully resident in smem; ONE barrier, 0 k-loop syncs.
// As: [M=128][K=128] pitch 132 floats (direct float4 copy, conflict-free).
// Bs: [K=128][N=128] pitch 132 floats, float4-XOR swizzle (c4 ^ (k&7)) ->
//     conflict-free STS.128 and LDS.128.
#define GBM 128
#define GBN 128
#define GPITCH 132                         // floats per row (33 float4)
#define GEMM_SMEM (2 * 128 * GPITCH * 4)   // 135168 B

__global__ __launch_bounds__(256) void k_gemm(const float* __restrict__ W) {
    extern __shared__ float sm[];
    float* As = sm;                        // [128][132]
    float* Bs = sm + 128 * GPITCH;         // [128][132] swizzled

    int tid = threadIdx.x;
    int m0 = blockIdx.y * GBM;
    int n0 = blockIdx.x * GBN;

    // load A tile (4096 float4) and B tile (4096 float4)
#pragma unroll
    for (int i = 0; i < 16; i++) {
        int idx = tid + i * 256;           // 0..4095
        int r = idx >> 5;                  // row
        int c4 = idx & 31;                 // float4 col
        float4 va = make_float4(0.f, 0.f, 0.f, 0.f);
        if (m0 + r < N_NODES) va = ((const float4*)g_X)[(m0 + r) * 32 + c4];
        ((float4*)(As + r * GPITCH))[c4] = va;
        float4 vb = *((const float4*)(W + r * HC + n0 + 4 * c4));
        ((float4*)(Bs + r * GPITCH))[c4 ^ (r & 7)] = vb;
    }
    __syncthreads();

    int tr = tid >> 4, tc = tid & 15;      // 16x16 threads, 8x8 each
    float acc[8][8];
#pragma unroll
    for (int i = 0; i < 8; i++)
#pragma unroll
        for (int j = 0; j < 8; j++) acc[i][j] = 0.f;

#pragma unroll 8
    for (int k = 0; k < 128; k++) {
        float a[8];
#pragma unroll
        for (int i = 0; i < 8; i++) a[i] = As[(tr * 8 + i) * GPITCH + k];
        int s = k & 7;
        float4 b0 = ((float4*)(Bs + k * GPITCH))[(2 * tc) ^ s];
        float4 b1 = ((float4*)(Bs + k * GPITCH))[(2 * tc + 1) ^ s];
        float b[8] = {b0.x, b0.y, b0.z, b0.w, b1.x, b1.y, b1.z, b1.w};
#pragma unroll
        for (int i = 0; i < 8; i++)
#pragma unroll
            for (int j = 0; j < 8; j++) acc[i][j] += a[i] * b[j];
    }

#pragma unroll
    for (int i = 0; i < 8; i++) {
        int r = m0 + tr * 8 + i;
        if (r < N_NODES) {
            float* dst = g_h + r * HC + n0 + tc * 8;
            *((float4*)dst) = make_float4(acc[i][0], acc[i][1], acc[i][2], acc[i][3]);
            *((float4*)(dst + 4)) = make_float4(acc[i][4], acc[i][5], acc[i][6], acc[i][7]);
        }
    }
}

// ------------------------- attention coefficients (float4, 2 nodes/block) -----
__global__ __launch_bounds__(256) void k_attn(const float* __restrict__ att_src,
                                              const float* __restrict__ att_dst) {
    int t = threadIdx.x & 127;
    int n = blockIdx.x * 2 + (threadIdx.x >> 7);
    int hd = t >> 5, lane = t & 31;
    float4 v = ((const float4*)g_h)[n * 128 + t];
    float4 a1 = ((const float4*)att_src)[hd * 32 + lane];
    float4 a2 = ((const float4*)att_dst)[hd * 32 + lane];
    float s1 = v.x * a1.x + v.y * a1.y + v.z * a1.z + v.w * a1.w;
    float s2 = v.x * a2.x + v.y * a2.y + v.z * a2.z + v.w * a2.w;
#pragma unroll
    for (int o = 16; o; o >>= 1) {
        s1 += __shfl_xor_sync(0xffffffffu, s1, o);
        s2 += __shfl_xor_sync(0xffffffffu, s2, o);
    }
    if (lane == 0) {
        g_as[n * HEADS + hd] = s1;
        g_ad[n * HEADS + hd] = s2;
    }
}

// ------------------------- scatter softmax (warp per node) --------------------
__global__ void k_softmax() {
    int warps_per_blk = blockDim.x >> 5;
    int n = blockIdx.x * warps_per_blk + (threadIdx.x >> 5);
    if (n >= N_NODES) return;
    int lane = threadIdx.x & 31;
    int st = g_off[n], en = g_off[n + 1];
    float4 ad4 = ((const float4*)g_ad)[n];
    float mx0 = -1e30f, mx1 = -1e30f, mx2 = -1e30f, mx3 = -1e30f;
    for (int p = st + lane; p < en; p += 32) {
        int s = g_csr_src[p];
        float4 as4 = ((const float4*)g_as)[s];
        float e0 = as4.x + ad4.x, e1 = as4.y + ad4.y, e2 = as4.z + ad4.z, e3 = as4.w + ad4.w;
        e0 = e0 > 0.f ? e0 : e0 * NEG_SLOPE;
        e1 = e1 > 0.f ? e1 : e1 * NEG_SLOPE;
        e2 = e2 > 0.f ? e2 : e2 * NEG_SLOPE;
        e3 = e3 > 0.f ? e3 : e3 * NEG_SLOPE;
        ((float4*)g_ex)[p] = make_float4(e0, e1, e2, e3);
        mx0 = fmaxf(mx0, e0); mx1 = fmaxf(mx1, e1);
        mx2 = fmaxf(mx2, e2); mx3 = fmaxf(mx3, e3);
    }
#pragma unroll
    for (int o = 16; o; o >>= 1) {
        mx0 = fmaxf(mx0, __shfl_xor_sync(0xffffffffu, mx0, o));
        mx1 = fmaxf(mx1, __shfl_xor_sync(0xffffffffu, mx1, o));
        mx2 = fmaxf(mx2, __shfl_xor_sync(0xffffffffu, mx2, o));
        mx3 = fmaxf(mx3, __shfl_xor_sync(0xffffffffu, mx3, o));
    }
    float s0 = 0.f, s1 = 0.f, s2 = 0.f, s3 = 0.f;
    for (int p = st + lane; p < en; p += 32) {
        float4 ev = ((const float4*)g_ex)[p];
        float x0 = __expf(ev.x - mx0), x1 = __expf(ev.y - mx1);
        float x2 = __expf(ev.z - mx2), x3 = __expf(ev.w - mx3);
        ((float4*)g_ex)[p] = make_float4(x0, x1, x2, x3);
        s0 += x0; s1 += x1; s2 += x2; s3 += x3;
    }
#pragma unroll
    for (int o = 16; o; o >>= 1) {
        s0 += __shfl_xor_sync(0xffffffffu, s0, o);
        s1 += __shfl_xor_sync(0xffffffffu, s1, o);
        s2 += __shfl_xor_sync(0xffffffffu, s2, o);
        s3 += __shfl_xor_sync(0xffffffffu, s3, o);
    }
    if (lane == 0) ((float4*)g_den)[n] = make_float4(s0, s1, s2, s3);
}

// ------------------------- aggregate + GraphCON update ------------------------
// Thread t owns flat channels [4t..4t+3] (one float4 of the h row, all within
// head t/32). Output channel t = mean(flat[4t..4t+3]) -> fully register-local:
// no shared memory, no block sync. Edge loop unrolled x4 for MLP.
__global__ __launch_bounds__(128) void k_aggregate(const float* __restrict__ bias,
                                                   float* __restrict__ out, int layer) {
    int n = blockIdx.x;
    int t = threadIdx.x;                 // 128
    int hd = t >> 5;
    int st = g_off[n], en = g_off[n + 1];
    const float4* h4 = (const float4*)g_h;
    float ax = 0.f, ay = 0.f, az = 0.f, aw = 0.f;
    int p = st;
    for (; p + 4 <= en; p += 4) {
        int s0 = g_csr_src[p],     s1 = g_csr_src[p + 1];
        int s2 = g_csr_src[p + 2], s3 = g_csr_src[p + 3];
        float e0 = g_ex[(p    ) * 4 + hd], e1 = g_ex[(p + 1) * 4 + hd];
        float e2 = g_ex[(p + 2) * 4 + hd], e3 = g_ex[(p + 3) * 4 + hd];
        float4 v0 = h4[s0 * 128 + t], v1 = h4[s1 * 128 + t];
        float4 v2 = h4[s2 * 128 + t], v3 = h4[s3 * 128 + t];
        ax += e0 * v0.x + e1 * v1.x + e2 * v2.x + e3 * v3.x;
        ay += e0 * v0.y + e1 * v1.y + e2 * v2.y + e3 * v3.y;
        az += e0 * v0.z + e1 * v1.z + e2 * v2.z + e3 * v3.z;
        aw += e0 * v0.w + e1 * v1.w + e2 * v2.w + e3 * v3.w;
    }
    for (; p < en; p++) {
        int s = g_csr_src[p];
        float e = g_ex[p * 4 + hd];
        float4 v = h4[s * 128 + t];
        ax += e * v.x; ay += e * v.y; az += e * v.z; aw += e * v.w;
    }
    float den = g_den[n * HEADS + hd];
    float inv = 1.0f / den;
    float4 b4 = ((const float4*)bias)[t];
    float g0 = ax * inv + b4.x;
    float g1 = ay * inv + b4.y;
    float g2 = az * inv + b4.z;
    float g3 = aw * inv + b4.w;
    g0 = g0 > 0.f ? g0 : (expf(g0) - 1.f);
    g1 = g1 > 0.f ? g1 : (expf(g1) - 1.f);
    g2 = g2 > 0.f ? g2 : (expf(g2) - 1.f);
    g3 = g3 > 0.f ? g3 : (expf(g3) - 1.f);
    float agg = 0.25f * (g0 + g1 + g2 + g3);
    float x = g_X[n * NHID + t];
    float y = g_Y[n * NHID + t];
    float y2 = y + DT * (agg - ALPHA * y - GAMMA * x);
    float x2 = x + DT * y2;
    g_X[n * NHID + t] = x2;
    g_Y[n * NHID + t] = y2;
    out[XALL_OFF + n * LSTRIDE + (layer + 1) * NHID + t] = x2;
    out[YALL_OFF + n * LSTRIDE + (layer + 1) * NHID + t] = y2;
}

// ------------------------- output projection ----------------------------------
__global__ void k_outproj(const float* __restrict__ Wr, const float* __restrict__ br,
                          float* __restrict__ out) {
    __shared__ float xs[NHID];
    int n = blockIdx.x;
    int t = threadIdx.x;                 // 128
    xs[t] = g_X[n * NHID + t];
    __syncthreads();
    if (t < NCLASS) {
        const float* w = Wr + t * NHID;
        float acc = 0.f;
#pragma unroll 8
        for (int k = 0; k < NHID; k++) acc += xs[k] * w[k];
        out[OUT_OFF + n * NCLASS + t] = acc + br[t];
    }
}

// ------------------------- launch ---------------------------------------------
extern "C" void kernel_launch(void* const* d_in, const int* in_sizes, int n_in,
                              void* d_out, int out_size) {
    const float* x       = (const float*)d_in[0];
    const int*   src     = (const int*)d_in[1];
    const int*   dst     = (const int*)d_in[2];
    const float* W       = (const float*)d_in[3];
    const float* att_src = (const float*)d_in[4];
    const float* att_dst = (const float*)d_in[5];
    const float* bias    = (const float*)d_in[6];
    const float* Wr      = (const float*)d_in[7];
    const float* br      = (const float*)d_in[8];
    float* out = (float*)d_out;

    cudaFuncSetAttribute(k_gemm, cudaFuncAttributeMaxDynamicSharedMemorySize, GEMM_SMEM);

    int *deg_p, *cur_p;
    cudaGetSymbolAddress((void**)&deg_p, g_deg);
    cudaGetSymbolAddress((void**)&cur_p, g_cursor);

    // ---- build CSR by destination (once per call) ----
    k_zero_int2<<<(N_NODES + 255) / 256, 256>>>(deg_p, cur_p, N_NODES);
    k_count_deg<<<(ETOT + 255) / 256, 256>>>(dst);
    k_scan<<<1, 1024>>>();
    k_scatter<<<(ETOT + 255) / 256, 256>>>(src, dst);

    // ---- init state ----
    k_init<<<N_NODES, NHID>>>(x, out);

    dim3 ggrid(HC / GBN, (N_NODES + GBM - 1) / GBM);   // (4, 157)
    for (int l = 0; l < NLAYERS; l++) {
        k_gemm<<<ggrid, 256, GEMM_SMEM>>>(W);
        k_attn<<<N_NODES / 2, 256>>>(att_src, att_dst);
        k_softmax<<<(N_NODES * 32 + 255) / 256, 256>>>();
        k_aggregate<<<N_NODES, 128>>>(bias, out, l);
    }
    k_outproj<<<N_NODES, 128>>>(Wr, br, out);
}

// round 4
// speedup vs baseline: 1.5944x; 1.5944x over previous
#include <cuda_runtime.h>
#include <math.h>

#define N_NODES 20000
#define NHID 128
#define HEADS 4
#define HC (HEADS * NHID)          // 512
#define E_EDGES 320000
#define ETOT (E_EDGES + N_NODES)   // 340000
#define NLAYERS 4
#define NCLASS 40
#define NEG_SLOPE 0.2f
#define DT 1.0f
#define ALPHA 1.0f
#define GAMMA 1.0f

// d_out layout: [out (N*NCLASS)] [X_all (N*(L+1)*C)] [Y_all (N*(L+1)*C)]
#define OUT_OFF   0
#define XALL_OFF  (N_NODES * NCLASS)
#define YALL_OFF  (XALL_OFF + N_NODES * (NLAYERS + 1) * NHID)
#define LSTRIDE   ((NLAYERS + 1) * NHID)   // 640 per node in X_all/Y_all

// ------------------------- device scratch (no allocs allowed) ----------------
__device__ float g_h[N_NODES * HC];          // 41 MB
__device__ float g_X[N_NODES * NHID];
__device__ float g_Y[N_NODES * NHID];
__device__ float g_as[N_NODES * HEADS];
__device__ float g_ad[N_NODES * HEADS];
__device__ float g_ex[ETOT * HEADS];         // per-CSR-position edge values
__device__ float g_den[N_NODES * HEADS];
__device__ int   g_deg[N_NODES];
__device__ int   g_cursor[N_NODES];
__device__ int   g_off[N_NODES + 1];
__device__ int   g_csr_src[ETOT];

// ------------------------- setup kernels -------------------------------------
__global__ void k_zero_int2(int* a, int* b, int n) {
    int i = blockIdx.x * blockDim.x + threadIdx.x;
    if (i < n) { a[i] = 0; b[i] = 0; }
}

__global__ void k_count_deg(const int* __restrict__ dst) {
    int e = blockIdx.x * blockDim.x + threadIdx.x;
    if (e >= ETOT) return;
    int d = (e < E_EDGES) ? dst[e] : (e - E_EDGES);
    atomicAdd(&g_deg[d], 1);
}

// single-block exclusive scan over g_deg -> g_off (N=20000)
__global__ void k_scan() {
    __shared__ int s[1024];
    const int CH = (N_NODES + 1023) / 1024;  // 20
    int tid = threadIdx.x;
    int base = tid * CH;
    int sum = 0;
    for (int i = 0; i < CH; i++) {
        int idx = base + i;
        if (idx < N_NODES) sum += g_deg[idx];
    }
    s[tid] = sum;
    __syncthreads();
    for (int d = 1; d < 1024; d <<= 1) {
        int v = (tid >= d) ? s[tid - d] : 0;
        __syncthreads();
        s[tid] += v;
        __syncthreads();
    }
    int run = (tid == 0) ? 0 : s[tid - 1];
    for (int i = 0; i < CH; i++) {
        int idx = base + i;
        if (idx < N_NODES) { g_off[idx] = run; run += g_deg[idx]; }
    }
    if (tid == 1023) g_off[N_NODES] = run;
}

__global__ void k_scatter(const int* __restrict__ src, const int* __restrict__ dst) {
    int e = blockIdx.x * blockDim.x + threadIdx.x;
    if (e >= ETOT) return;
    int d, s;
    if (e < E_EDGES) { d = dst[e]; s = src[e]; }
    else { d = e - E_EDGES; s = d; }
    int pos = g_off[d] + atomicAdd(&g_cursor[d], 1);
    g_csr_src[pos] = s;
}

// init state + write layer-0 slices of X_all / Y_all
__global__ void k_init(const float* __restrict__ x, float* __restrict__ out) {
    int n = blockIdx.x;
    int t = threadIdx.x;
    float v = x[n * NHID + t];
    g_X[n * NHID + t] = v;
    g_Y[n * NHID + t] = v;
    out[XALL_OFF + n * LSTRIDE + t] = v;
    out[YALL_OFF + n * LSTRIDE + t] = v;
}

// ------------------------- FFMA GEMM: h = X @ W -------------------------------
// C[20000 x 512] = X[20000 x 128] @ W[128 x 512], row-major fp32.
// Tiles 128x128, BK=16, smem 16.9 KB -> 2 CTAs/SM (16 warps), 8 stages.
// As: [k][m] (pitch 132) -> a-frag reads are 2-address broadcast, banks差8: free.
// Bs: [k][n] (pitch 132); thread tc owns columns {tc+16j} -> b-frag reads are
//     16-consecutive-float scalar LDS, conflict-free.
#define GBM 128
#define GBN 128
#define BKS 16
#define GP 132

__global__ __launch_bounds__(256, 2) void k_gemm(const float* __restrict__ W) {
    __shared__ float As[BKS * GP];     // [k][m]
    __shared__ float Bs[BKS * GP];     // [k][n]

    int tid = threadIdx.x;
    int m0 = blockIdx.y * GBM;
    int n0 = blockIdx.x * GBN;
    int tr = tid >> 4, tc = tid & 15;

    float acc[8][8];
#pragma unroll
    for (int i = 0; i < 8; i++)
#pragma unroll
        for (int j = 0; j < 8; j++) acc[i][j] = 0.f;

    for (int k0 = 0; k0 < NHID; k0 += BKS) {
        __syncthreads();
        // A stage: 128 m-rows x 4 float4 (k0..k0+15) = 512 float4, transpose to [k][m]
#pragma unroll
        for (int i = 0; i < 2; i++) {
            int idx = tid + i * 256;           // 0..511
            int r = idx >> 2;                  // m row
            int c4 = idx & 3;                  // float4 within the 16 k's
            float4 v = make_float4(0.f, 0.f, 0.f, 0.f);
            if (m0 + r < N_NODES) v = ((const float4*)g_X)[(m0 + r) * 32 + (k0 >> 2) + c4];
            As[(c4 * 4 + 0) * GP + r] = v.x;
            As[(c4 * 4 + 1) * GP + r] = v.y;
            As[(c4 * 4 + 2) * GP + r] = v.z;
            As[(c4 * 4 + 3) * GP + r] = v.w;
        }
        // B stage: 16 k-rows x 32 float4 = 512 float4, direct copy
#pragma unroll
        for (int i = 0; i < 2; i++) {
            int idx = tid + i * 256;
            int kk = idx >> 5;
            int c4 = idx & 31;
            float4 v = *((const float4*)(W + (k0 + kk) * HC + n0 + 4 * c4));
            ((float4*)(Bs + kk * GP))[c4] = v;
        }
        __syncthreads();

#pragma unroll
        for (int kk = 0; kk < BKS; kk++) {
            float a[8], b[8];
#pragma unroll
            for (int i = 0; i < 8; i++) a[i] = As[kk * GP + tr * 8 + i];
#pragma unroll
            for (int j = 0; j < 8; j++) b[j] = Bs[kk * GP + tc + 16 * j];
#pragma unroll
            for (int i = 0; i < 8; i++)
#pragma unroll
                for (int j = 0; j < 8; j++) acc[i][j] += a[i] * b[j];
        }
    }

#pragma unroll
    for (int i = 0; i < 8; i++) {
        int r = m0 + tr * 8 + i;
        if (r < N_NODES) {
            float* dstp = g_h + r * HC + n0 + tc;
#pragma unroll
            for (int j = 0; j < 8; j++) dstp[16 * j] = acc[i][j];
        }
    }
}

// ------------------------- attention coefficients (float4, 2 nodes/block) -----
__global__ __launch_bounds__(256) void k_attn(const float* __restrict__ att_src,
                                              const float* __restrict__ att_dst) {
    int t = threadIdx.x & 127;
    int n = blockIdx.x * 2 + (threadIdx.x >> 7);
    int hd = t >> 5, lane = t & 31;
    float4 v = ((const float4*)g_h)[n * 128 + t];
    float4 a1 = ((const float4*)att_src)[hd * 32 + lane];
    float4 a2 = ((const float4*)att_dst)[hd * 32 + lane];
    float s1 = v.x * a1.x + v.y * a1.y + v.z * a1.z + v.w * a1.w;
    float s2 = v.x * a2.x + v.y * a2.y + v.z * a2.z + v.w * a2.w;
#pragma unroll
    for (int o = 16; o; o >>= 1) {
        s1 += __shfl_xor_sync(0xffffffffu, s1, o);
        s2 += __shfl_xor_sync(0xffffffffu, s2, o);
    }
    if (lane == 0) {
        g_as[n * HEADS + hd] = s1;
        g_ad[n * HEADS + hd] = s2;
    }
}

// ------------------------- scatter softmax (warp per node) --------------------
__global__ void k_softmax() {
    int warps_per_blk = blockDim.x >> 5;
    int n = blockIdx.x * warps_per_blk + (threadIdx.x >> 5);
    if (n >= N_NODES) return;
    int lane = threadIdx.x & 31;
    int st = g_off[n], en = g_off[n + 1];
    float4 ad4 = ((const float4*)g_ad)[n];
    float mx0 = -1e30f, mx1 = -1e30f, mx2 = -1e30f, mx3 = -1e30f;
    for (int p = st + lane; p < en; p += 32) {
        int s = g_csr_src[p];
        float4 as4 = ((const float4*)g_as)[s];
        float e0 = as4.x + ad4.x, e1 = as4.y + ad4.y, e2 = as4.z + ad4.z, e3 = as4.w + ad4.w;
        e0 = e0 > 0.f ? e0 : e0 * NEG_SLOPE;
        e1 = e1 > 0.f ? e1 : e1 * NEG_SLOPE;
        e2 = e2 > 0.f ? e2 : e2 * NEG_SLOPE;
        e3 = e3 > 0.f ? e3 : e3 * NEG_SLOPE;
        ((float4*)g_ex)[p] = make_float4(e0, e1, e2, e3);
        mx0 = fmaxf(mx0, e0); mx1 = fmaxf(mx1, e1);
        mx2 = fmaxf(mx2, e2); mx3 = fmaxf(mx3, e3);
    }
#pragma unroll
    for (int o = 16; o; o >>= 1) {
        mx0 = fmaxf(mx0, __shfl_xor_sync(0xffffffffu, mx0, o));
        mx1 = fmaxf(mx1, __shfl_xor_sync(0xffffffffu, mx1, o));
        mx2 = fmaxf(mx2, __shfl_xor_sync(0xffffffffu, mx2, o));
        mx3 = fmaxf(mx3, __shfl_xor_sync(0xffffffffu, mx3, o));
    }
    float s0 = 0.f, s1 = 0.f, s2 = 0.f, s3 = 0.f;
    for (int p = st + lane; p < en; p += 32) {
        float4 ev = ((const float4*)g_ex)[p];
        float x0 = __expf(ev.x - mx0), x1 = __expf(ev.y - mx1);
        float x2 = __expf(ev.z - mx2), x3 = __expf(ev.w - mx3);
        ((float4*)g_ex)[p] = make_float4(x0, x1, x2, x3);
        s0 += x0; s1 += x1; s2 += x2; s3 += x3;
    }
#pragma unroll
    for (int o = 16; o; o >>= 1) {
        s0 += __shfl_xor_sync(0xffffffffu, s0, o);
        s1 += __shfl_xor_sync(0xffffffffu, s1, o);
        s2 += __shfl_xor_sync(0xffffffffu, s2, o);
        s3 += __shfl_xor_sync(0xffffffffu, s3, o);
    }
    if (lane == 0) ((float4*)g_den)[n] = make_float4(s0, s1, s2, s3);
}

// ------------------------- aggregate + GraphCON update ------------------------
// Thread t owns flat channels [4t..4t+3]; head-mean/ELU/update register-local.
__global__ __launch_bounds__(128) void k_aggregate(const float* __restrict__ bias,
                                                   float* __restrict__ out, int layer) {
    int n = blockIdx.x;
    int t = threadIdx.x;                 // 128
    int hd = t >> 5;
    int st = g_off[n], en = g_off[n + 1];
    const float4* h4 = (const float4*)g_h;
    float ax = 0.f, ay = 0.f, az = 0.f, aw = 0.f;
    int p = st;
    for (; p + 4 <= en; p += 4) {
        int s0 = g_csr_src[p],     s1 = g_csr_src[p + 1];
        int s2 = g_csr_src[p + 2], s3 = g_csr_src[p + 3];
        float e0 = g_ex[(p    ) * 4 + hd], e1 = g_ex[(p + 1) * 4 + hd];
        float e2 = g_ex[(p + 2) * 4 + hd], e3 = g_ex[(p + 3) * 4 + hd];
        float4 v0 = h4[s0 * 128 + t], v1 = h4[s1 * 128 + t];
        float4 v2 = h4[s2 * 128 + t], v3 = h4[s3 * 128 + t];
        ax += e0 * v0.x + e1 * v1.x + e2 * v2.x + e3 * v3.x;
        ay += e0 * v0.y + e1 * v1.y + e2 * v2.y + e3 * v3.y;
        az += e0 * v0.z + e1 * v1.z + e2 * v2.z + e3 * v3.z;
        aw += e0 * v0.w + e1 * v1.w + e2 * v2.w + e3 * v3.w;
    }
    for (; p < en; p++) {
        int s = g_csr_src[p];
        float e = g_ex[p * 4 + hd];
        float4 v = h4[s * 128 + t];
        ax += e * v.x; ay += e * v.y; az += e * v.z; aw += e * v.w;
    }
    float den = g_den[n * HEADS + hd];
    float inv = 1.0f / den;
    float4 b4 = ((const float4*)bias)[t];
    float g0 = ax * inv + b4.x;
    float g1 = ay * inv + b4.y;
    float g2 = az * inv + b4.z;
    float g3 = aw * inv + b4.w;
    g0 = g0 > 0.f ? g0 : (expf(g0) - 1.f);
    g1 = g1 > 0.f ? g1 : (expf(g1) - 1.f);
    g2 = g2 > 0.f ? g2 : (expf(g2) - 1.f);
    g3 = g3 > 0.f ? g3 : (expf(g3) - 1.f);
    float agg = 0.25f * (g0 + g1 + g2 + g3);
    float x = g_X[n * NHID + t];
    float y = g_Y[n * NHID + t];
    float y2 = y + DT * (agg - ALPHA * y - GAMMA * x);
    float x2 = x + DT * y2;
    g_X[n * NHID + t] = x2;
    g_Y[n * NHID + t] = y2;
    out[XALL_OFF + n * LSTRIDE + (layer + 1) * NHID + t] = x2;
    out[YALL_OFF + n * LSTRIDE + (layer + 1) * NHID + t] = y2;
}

// ------------------------- output projection ----------------------------------
__global__ void k_outproj(const float* __restrict__ Wr, const float* __restrict__ br,
                          float* __restrict__ out) {
    __shared__ float xs[NHID];
    int n = blockIdx.x;
    int t = threadIdx.x;                 // 128
    xs[t] = g_X[n * NHID + t];
    __syncthreads();
    if (t < NCLASS) {
        const float* w = Wr + t * NHID;
        float acc = 0.f;
#pragma unroll 8
        for (int k = 0; k < NHID; k++) acc += xs[k] * w[k];
        out[OUT_OFF + n * NCLASS + t] = acc + br[t];
    }
}

// ------------------------- launch ---------------------------------------------
extern "C" void kernel_launch(void* const* d_in, const int* in_sizes, int n_in,
                              void* d_out, int out_size) {
    const float* x       = (const float*)d_in[0];
    const int*   src     = (const int*)d_in[1];
    const int*   dst     = (const int*)d_in[2];
    const float* W       = (const float*)d_in[3];
    const float* att_src = (const float*)d_in[4];
    const float* att_dst = (const float*)d_in[5];
    const float* bias    = (const float*)d_in[6];
    const float* Wr      = (const float*)d_in[7];
    const float* br      = (const float*)d_in[8];
    float* out = (float*)d_out;

    int *deg_p, *cur_p;
    cudaGetSymbolAddress((void**)&deg_p, g_deg);
    cudaGetSymbolAddress((void**)&cur_p, g_cursor);

    // ---- build CSR by destination (once per call) ----
    k_zero_int2<<<(N_NODES + 255) / 256, 256>>>(deg_p, cur_p, N_NODES);
    k_count_deg<<<(ETOT + 255) / 256, 256>>>(dst);
    k_scan<<<1, 1024>>>();
    k_scatter<<<(ETOT + 255) / 256, 256>>>(src, dst);

    // ---- init state ----
    k_init<<<N_NODES, NHID>>>(x, out);

    dim3 ggrid(HC / GBN, (N_NODES + GBM - 1) / GBM);   // (4, 157)
    for (int l = 0; l < NLAYERS; l++) {
        k_gemm<<<ggrid, 256>>>(W);
        k_attn<<<N_NODES / 2, 256>>>(att_src, att_dst);
        k_softmax<<<(N_NODES * 32 + 255) / 256, 256>>>();
        k_aggregate<<<N_NODES, 128>>>(bias, out, l);
    }
    k_outproj<<<N_NODES, 128>>>(Wr, br, out);
}

// round 5
// speedup vs baseline: 1.6204x; 1.0163x over previous
#include <cuda_runtime.h>
#include <math.h>

#define N_NODES 20000
#define NHID 128
#define HEADS 4
#define HC (HEADS * NHID)          // 512
#define E_EDGES 320000
#define ETOT (E_EDGES + N_NODES)   // 340000
#define NLAYERS 4
#define NCLASS 40
#define NEG_SLOPE 0.2f
#define DT 1.0f
#define ALPHA 1.0f
#define GAMMA 1.0f

// d_out layout: [out (N*NCLASS)] [X_all (N*(L+1)*C)] [Y_all (N*(L+1)*C)]
#define OUT_OFF   0
#define XALL_OFF  (N_NODES * NCLASS)
#define YALL_OFF  (XALL_OFF + N_NODES * (NLAYERS + 1) * NHID)
#define LSTRIDE   ((NLAYERS + 1) * NHID)   // 640 per node in X_all/Y_all

// ------------------------- device scratch (no allocs allowed) ----------------
__device__ float g_h[N_NODES * HC];          // 41 MB
__device__ float g_X[N_NODES * NHID];
__device__ float g_Y[N_NODES * NHID];
__device__ float g_as[N_NODES * HEADS];
__device__ float g_ad[N_NODES * HEADS];
__device__ int   g_deg[N_NODES];
__device__ int   g_cursor[N_NODES];
__device__ int   g_off[N_NODES + 1];
__device__ int   g_csr_src[ETOT];

// ------------------------- setup kernels -------------------------------------
__global__ void k_zero_int2(int* a, int* b, int n) {
    int i = blockIdx.x * blockDim.x + threadIdx.x;
    if (i < n) { a[i] = 0; b[i] = 0; }
}

__global__ void k_count_deg(const int* __restrict__ dst) {
    int e = blockIdx.x * blockDim.x + threadIdx.x;
    if (e >= ETOT) return;
    int d = (e < E_EDGES) ? dst[e] : (e - E_EDGES);
    atomicAdd(&g_deg[d], 1);
}

// single-block exclusive scan over g_deg -> g_off (N=20000)
__global__ void k_scan() {
    __shared__ int s[1024];
    const int CH = (N_NODES + 1023) / 1024;  // 20
    int tid = threadIdx.x;
    int base = tid * CH;
    int sum = 0;
    for (int i = 0; i < CH; i++) {
        int idx = base + i;
        if (idx < N_NODES) sum += g_deg[idx];
    }
    s[tid] = sum;
    __syncthreads();
    for (int d = 1; d < 1024; d <<= 1) {
        int v = (tid >= d) ? s[tid - d] : 0;
        __syncthreads();
        s[tid] += v;
        __syncthreads();
    }
    int run = (tid == 0) ? 0 : s[tid - 1];
    for (int i = 0; i < CH; i++) {
        int idx = base + i;
        if (idx < N_NODES) { g_off[idx] = run; run += g_deg[idx]; }
    }
    if (tid == 1023) g_off[N_NODES] = run;
}

__global__ void k_scatter(const int* __restrict__ src, const int* __restrict__ dst) {
    int e = blockIdx.x * blockDim.x + threadIdx.x;
    if (e >= ETOT) return;
    int d, s;
    if (e < E_EDGES) { d = dst[e]; s = src[e]; }
    else { d = e - E_EDGES; s = d; }
    int pos = g_off[d] + atomicAdd(&g_cursor[d], 1);
    g_csr_src[pos] = s;
}

// init state + write layer-0 slices of X_all / Y_all
__global__ void k_init(const float* __restrict__ x, float* __restrict__ out) {
    int n = blockIdx.x;
    int t = threadIdx.x;
    float v = x[n * NHID + t];
    g_X[n * NHID + t] = v;
    g_Y[n * NHID + t] = v;
    out[XALL_OFF + n * LSTRIDE + t] = v;
    out[YALL_OFF + n * LSTRIDE + t] = v;
}

// ------------------------- FFMA GEMM + fused attention dots -------------------
// C[20000 x 512] = X[20000 x 128] @ W[128 x 512], row-major fp32.
// Tiles 128x128, BK=16, smem 16.9 KB -> 2 CTAs/SM. Block bn covers exactly
// head bn's 128 channels, so a_s/a_d dot products are computed in-register in
// the epilogue (width-16 shuffle reduce across the threads sharing a row).
#define GBM 128
#define GBN 128
#define BKS 16
#define GP 132

__global__ __launch_bounds__(256, 2) void k_gemm(const float* __restrict__ W,
                                                 const float* __restrict__ att_src,
                                                 const float* __restrict__ att_dst) {
    __shared__ float As[BKS * GP];     // [k][m]
    __shared__ float Bs[BKS * GP];     // [k][n]

    int tid = threadIdx.x;
    int m0 = blockIdx.y * GBM;
    int n0 = blockIdx.x * GBN;        // == head * NHID
    int head = blockIdx.x;
    int tr = tid >> 4, tc = tid & 15;

    float acc[8][8];
#pragma unroll
    for (int i = 0; i < 8; i++)
#pragma unroll
        for (int j = 0; j < 8; j++) acc[i][j] = 0.f;

    for (int k0 = 0; k0 < NHID; k0 += BKS) {
        __syncthreads();
        // A stage: 128 m-rows x 4 float4 (k0..k0+15) = 512 float4, transpose to [k][m]
#pragma unroll
        for (int i = 0; i < 2; i++) {
            int idx = tid + i * 256;           // 0..511
            int r = idx >> 2;                  // m row
            int c4 = idx & 3;                  // float4 within the 16 k's
            float4 v = make_float4(0.f, 0.f, 0.f, 0.f);
            if (m0 + r < N_NODES) v = ((const float4*)g_X)[(m0 + r) * 32 + (k0 >> 2) + c4];
            As[(c4 * 4 + 0) * GP + r] = v.x;
            As[(c4 * 4 + 1) * GP + r] = v.y;
            As[(c4 * 4 + 2) * GP + r] = v.z;
            As[(c4 * 4 + 3) * GP + r] = v.w;
        }
        // B stage: 16 k-rows x 32 float4 = 512 float4, direct copy
#pragma unroll
        for (int i = 0; i < 2; i++) {
            int idx = tid + i * 256;
            int kk = idx >> 5;
            int c4 = idx & 31;
            float4 v = *((const float4*)(W + (k0 + kk) * HC + n0 + 4 * c4));
            ((float4*)(Bs + kk * GP))[c4] = v;
        }
        __syncthreads();

#pragma unroll
        for (int kk = 0; kk < BKS; kk++) {
            float a[8], b[8];
#pragma unroll
            for (int i = 0; i < 8; i++) a[i] = As[kk * GP + tr * 8 + i];
#pragma unroll
            for (int j = 0; j < 8; j++) b[j] = Bs[kk * GP + tc + 16 * j];
#pragma unroll
            for (int i = 0; i < 8; i++)
#pragma unroll
                for (int j = 0; j < 8; j++) acc[i][j] += a[i] * b[j];
        }
    }

    // store h + fused attention dots
    float asv[8], adv[8];
#pragma unroll
    for (int j = 0; j < 8; j++) {
        asv[j] = att_src[n0 + tc + 16 * j];
        adv[j] = att_dst[n0 + tc + 16 * j];
    }
#pragma unroll
    for (int i = 0; i < 8; i++) {
        int r = m0 + tr * 8 + i;
        bool valid = (r < N_NODES);
        if (valid) {
            float* dstp = g_h + r * HC + n0 + tc;
#pragma unroll
            for (int j = 0; j < 8; j++) dstp[16 * j] = acc[i][j];
        }
        float s1 = 0.f, s2 = 0.f;
#pragma unroll
        for (int j = 0; j < 8; j++) { s1 += acc[i][j] * asv[j]; s2 += acc[i][j] * adv[j]; }
#pragma unroll
        for (int o = 8; o; o >>= 1) {
            s1 += __shfl_down_sync(0xffffffffu, s1, o, 16);
            s2 += __shfl_down_sync(0xffffffffu, s2, o, 16);
        }
        if (tc == 0 && valid) {
            g_as[r * HEADS + head] = s1;
            g_ad[r * HEADS + head] = s2;
        }
    }
}

// ------------------------- fused softmax + aggregate + GraphCON update --------
// No-max softmax: e = leakyrelu(a_s+a_d) is bounded (|e| ~ <= 15 << 88), so
// sum(exp(e)*h)/sum(exp(e)) == reference's max-subtracted form exactly (up to
// fp rounding). Block per node, 128 threads; thread t owns flat channels
// [4t..4t+3] (head t/32), so head-mean/ELU/update stay register-local.
#define ACHUNK 128
__global__ __launch_bounds__(128) void k_aggregate(const float* __restrict__ bias,
                                                   float* __restrict__ out, int layer) {
    __shared__ int    s_src[ACHUNK];
    __shared__ float  s_ex[ACHUNK * 4];
    __shared__ float4 s_den[4];

    int n = blockIdx.x;
    int t = threadIdx.x;                 // 128
    int hd = t >> 5, lane = t & 31;
    int st = g_off[n], en = g_off[n + 1];
    float4 ad4 = ((const float4*)g_ad)[n];
    const float4* h4 = (const float4*)g_h;

    float4 denp = make_float4(0.f, 0.f, 0.f, 0.f);
    float ax = 0.f, ay = 0.f, az = 0.f, aw = 0.f;

    for (int c0 = st; c0 < en; c0 += ACHUNK) {
        int cl = en - c0; if (cl > ACHUNK) cl = ACHUNK;
        // phase A: compute exp(e) for this chunk's edges
        if (t < cl) {
            int s = g_csr_src[c0 + t];
            float4 as4 = ((const float4*)g_as)[s];
            float e0 = as4.x + ad4.x, e1 = as4.y + ad4.y;
            float e2 = as4.z + ad4.z, e3 = as4.w + ad4.w;
            e0 = e0 > 0.f ? e0 : e0 * NEG_SLOPE;
            e1 = e1 > 0.f ? e1 : e1 * NEG_SLOPE;
            e2 = e2 > 0.f ? e2 : e2 * NEG_SLOPE;
            e3 = e3 > 0.f ? e3 : e3 * NEG_SLOPE;
            float x0 = __expf(e0), x1 = __expf(e1), x2 = __expf(e2), x3 = __expf(e3);
            s_src[t] = s;
            ((float4*)s_ex)[t] = make_float4(x0, x1, x2, x3);
            denp.x += x0; denp.y += x1; denp.z += x2; denp.w += x3;
        }
        __syncthreads();
        // phase B: gather-accumulate (smem reads are warp-broadcast)
        int j = 0;
        for (; j + 4 <= cl; j += 4) {
            int s0 = s_src[j], s1 = s_src[j + 1], s2 = s_src[j + 2], s3 = s_src[j + 3];
            float e0 = s_ex[(j    ) * 4 + hd], e1 = s_ex[(j + 1) * 4 + hd];
            float e2 = s_ex[(j + 2) * 4 + hd], e3 = s_ex[(j + 3) * 4 + hd];
            float4 v0 = h4[s0 * 128 + t], v1 = h4[s1 * 128 + t];
            float4 v2 = h4[s2 * 128 + t], v3 = h4[s3 * 128 + t];
            ax += e0 * v0.x + e1 * v1.x + e2 * v2.x + e3 * v3.x;
            ay += e0 * v0.y + e1 * v1.y + e2 * v2.y + e3 * v3.y;
            az += e0 * v0.z + e1 * v1.z + e2 * v2.z + e3 * v3.z;
            aw += e0 * v0.w + e1 * v1.w + e2 * v2.w + e3 * v3.w;
        }
        for (; j < cl; j++) {
            int s = s_src[j];
            float e = s_ex[j * 4 + hd];
            float4 v = h4[s * 128 + t];
            ax += e * v.x; ay += e * v.y; az += e * v.z; aw += e * v.w;
        }
        __syncthreads();
    }

    // block-reduce den (warp shfl then cross-warp via smem)
#pragma unroll
    for (int o = 16; o; o >>= 1) {
        denp.x += __shfl_xor_sync(0xffffffffu, denp.x, o);
        denp.y += __shfl_xor_sync(0xffffffffu, denp.y, o);
        denp.z += __shfl_xor_sync(0xffffffffu, denp.z, o);
        denp.w += __shfl_xor_sync(0xffffffffu, denp.w, o);
    }
    if (lane == 0) s_den[hd] = denp;
    __syncthreads();
    float4 d0 = s_den[0], d1 = s_den[1], d2 = s_den[2], d3 = s_den[3];
    float dens[4] = {d0.x + d1.x + d2.x + d3.x, d0.y + d1.y + d2.y + d3.y,
                     d0.z + d1.z + d2.z + d3.z, d0.w + d1.w + d2.w + d3.w};
    float inv = 1.0f / dens[hd];

    float4 b4 = ((const float4*)bias)[t];
    float g0 = ax * inv + b4.x;
    float g1 = ay * inv + b4.y;
    float g2 = az * inv + b4.z;
    float g3 = aw * inv + b4.w;
    g0 = g0 > 0.f ? g0 : (expf(g0) - 1.f);
    g1 = g1 > 0.f ? g1 : (expf(g1) - 1.f);
    g2 = g2 > 0.f ? g2 : (expf(g2) - 1.f);
    g3 = g3 > 0.f ? g3 : (expf(g3) - 1.f);
    float agg = 0.25f * (g0 + g1 + g2 + g3);
    float x = g_X[n * NHID + t];
    float y = g_Y[n * NHID + t];
    float y2 = y + DT * (agg - ALPHA * y - GAMMA * x);
    float x2 = x + DT * y2;
    g_X[n * NHID + t] = x2;
    g_Y[n * NHID + t] = y2;
    out[XALL_OFF + n * LSTRIDE + (layer + 1) * NHID + t] = x2;
    out[YALL_OFF + n * LSTRIDE + (layer + 1) * NHID + t] = y2;
}

// ------------------------- output projection ----------------------------------
__global__ void k_outproj(const float* __restrict__ Wr, const float* __restrict__ br,
                          float* __restrict__ out) {
    __shared__ float xs[NHID];
    int n = blockIdx.x;
    int t = threadIdx.x;                 // 128
    xs[t] = g_X[n * NHID + t];
    __syncthreads();
    if (t < NCLASS) {
        const float* w = Wr + t * NHID;
        float acc = 0.f;
#pragma unroll 8
        for (int k = 0; k < NHID; k++) acc += xs[k] * w[k];
        out[OUT_OFF + n * NCLASS + t] = acc + br[t];
    }
}

// ------------------------- launch ---------------------------------------------
extern "C" void kernel_launch(void* const* d_in, const int* in_sizes, int n_in,
                              void* d_out, int out_size) {
    const float* x       = (const float*)d_in[0];
    const int*   src     = (const int*)d_in[1];
    const int*   dst     = (const int*)d_in[2];
    const float* W       = (const float*)d_in[3];
    const float* att_src = (const float*)d_in[4];
    const float* att_dst = (const float*)d_in[5];
    const float* bias    = (const float*)d_in[6];
    const float* Wr      = (const float*)d_in[7];
    const float* br      = (const float*)d_in[8];
    float* out = (float*)d_out;

    int *deg_p, *cur_p;
    cudaGetSymbolAddress((void**)&deg_p, g_deg);
    cudaGetSymbolAddress((void**)&cur_p, g_cursor);

    // ---- build CSR by destination (once per call) ----
    k_zero_int2<<<(N_NODES + 255) / 256, 256>>>(deg_p, cur_p, N_NODES);
    k_count_deg<<<(ETOT + 255) / 256, 256>>>(dst);
    k_scan<<<1, 1024>>>();
    k_scatter<<<(ETOT + 255) / 256, 256>>>(src, dst);

    // ---- init state ----
    k_init<<<N_NODES, NHID>>>(x, out);

    dim3 ggrid(HC / GBN, (N_NODES + GBM - 1) / GBM);   // (4, 157)
    for (int l = 0; l < NLAYERS; l++) {
        k_gemm<<<ggrid, 256>>>(W, att_src, att_dst);
        k_aggregate<<<N_NODES, 128>>>(bias, out, l);
    }
    k_outproj<<<N_NODES, 128>>>(Wr, br, out);
}

// round 6
// speedup vs baseline: 1.7950x; 1.1078x over previous
#include <cuda_runtime.h>
#include <cuda_fp16.h>
#include <math.h>

#define N_NODES 20000
#define NHID 128
#define HEADS 4
#define HC (HEADS * NHID)          // 512
#define E_EDGES 320000
#define ETOT (E_EDGES + N_NODES)   // 340000
#define NLAYERS 4
#define NCLASS 40
#define NEG_SLOPE 0.2f
#define DT 1.0f
#define ALPHA 1.0f
#define GAMMA 1.0f

// d_out layout: [out (N*NCLASS)] [X_all (N*(L+1)*C)] [Y_all (N*(L+1)*C)]
#define OUT_OFF   0
#define XALL_OFF  (N_NODES * NCLASS)
#define YALL_OFF  (XALL_OFF + N_NODES * (NLAYERS + 1) * NHID)
#define LSTRIDE   ((NLAYERS + 1) * NHID)   // 640 per node in X_all/Y_all

// ------------------------- device scratch (no allocs allowed) ----------------
__device__ __half g_hh[N_NODES * HC];        // 20.5 MB (fp16 messages)
__device__ float g_X[N_NODES * NHID];
__device__ float g_Y[N_NODES * NHID];
__device__ float g_as[N_NODES * HEADS];
__device__ float g_ad[N_NODES * HEADS];
__device__ int   g_deg[N_NODES];
__device__ int   g_cursor[N_NODES];
__device__ int   g_off[N_NODES + 1];
__device__ int   g_csr_src[ETOT];

// ------------------------- setup kernels -------------------------------------
__global__ void k_zero_int2(int* a, int* b, int n) {
    int i = blockIdx.x * blockDim.x + threadIdx.x;
    if (i < n) { a[i] = 0; b[i] = 0; }
}

__global__ void k_count_deg(const int* __restrict__ dst) {
    int e = blockIdx.x * blockDim.x + threadIdx.x;
    if (e >= ETOT) return;
    int d = (e < E_EDGES) ? dst[e] : (e - E_EDGES);
    atomicAdd(&g_deg[d], 1);
}

// single-block exclusive scan over g_deg -> g_off (N=20000)
__global__ void k_scan() {
    __shared__ int s[1024];
    const int CH = (N_NODES + 1023) / 1024;  // 20
    int tid = threadIdx.x;
    int base = tid * CH;
    int sum = 0;
    for (int i = 0; i < CH; i++) {
        int idx = base + i;
        if (idx < N_NODES) sum += g_deg[idx];
    }
    s[tid] = sum;
    __syncthreads();
    for (int d = 1; d < 1024; d <<= 1) {
        int v = (tid >= d) ? s[tid - d] : 0;
        __syncthreads();
        s[tid] += v;
        __syncthreads();
    }
    int run = (tid == 0) ? 0 : s[tid - 1];
    for (int i = 0; i < CH; i++) {
        int idx = base + i;
        if (idx < N_NODES) { g_off[idx] = run; run += g_deg[idx]; }
    }
    if (tid == 1023) g_off[N_NODES] = run;
}

__global__ void k_scatter(const int* __restrict__ src, const int* __restrict__ dst) {
    int e = blockIdx.x * blockDim.x + threadIdx.x;
    if (e >= ETOT) return;
    int d, s;
    if (e < E_EDGES) { d = dst[e]; s = src[e]; }
    else { d = e - E_EDGES; s = d; }
    int pos = g_off[d] + atomicAdd(&g_cursor[d], 1);
    g_csr_src[pos] = s;
}

// init state + write layer-0 slices of X_all / Y_all
__global__ void k_init(const float* __restrict__ x, float* __restrict__ out) {
    int n = blockIdx.x;
    int t = threadIdx.x;
    float v = x[n * NHID + t];
    g_X[n * NHID + t] = v;
    g_Y[n * NHID + t] = v;
    out[XALL_OFF + n * LSTRIDE + t] = v;
    out[YALL_OFF + n * LSTRIDE + t] = v;
}

// ------------------------- FFMA GEMM + fused attention dots -------------------
// C[20000 x 512] = X[20000 x 128] @ W[128 x 512], row-major fp32 compute.
// Tiles 128x128, BK=16, smem 16.9 KB -> 2 CTAs/SM. Block bn covers exactly
// head bn's 128 channels: a_s/a_d dots computed in-register from the fp32
// accumulators (full precision), h stored quantized to fp16.
#define GBM 128
#define GBN 128
#define BKS 16
#define GP 132

__global__ __launch_bounds__(256, 2) void k_gemm(const float* __restrict__ W,
                                                 const float* __restrict__ att_src,
                                                 const float* __restrict__ att_dst) {
    __shared__ float As[BKS * GP];     // [k][m]
    __shared__ float Bs[BKS * GP];     // [k][n]

    int tid = threadIdx.x;
    int m0 = blockIdx.y * GBM;
    int n0 = blockIdx.x * GBN;        // == head * NHID
    int head = blockIdx.x;
    int tr = tid >> 4, tc = tid & 15;

    float acc[8][8];
#pragma unroll
    for (int i = 0; i < 8; i++)
#pragma unroll
        for (int j = 0; j < 8; j++) acc[i][j] = 0.f;

    for (int k0 = 0; k0 < NHID; k0 += BKS) {
        __syncthreads();
        // A stage: transpose to [k][m]
#pragma unroll
        for (int i = 0; i < 2; i++) {
            int idx = tid + i * 256;           // 0..511
            int r = idx >> 2;                  // m row
            int c4 = idx & 3;                  // float4 within the 16 k's
            float4 v = make_float4(0.f, 0.f, 0.f, 0.f);
            if (m0 + r < N_NODES) v = ((const float4*)g_X)[(m0 + r) * 32 + (k0 >> 2) + c4];
            As[(c4 * 4 + 0) * GP + r] = v.x;
            As[(c4 * 4 + 1) * GP + r] = v.y;
            As[(c4 * 4 + 2) * GP + r] = v.z;
            As[(c4 * 4 + 3) * GP + r] = v.w;
        }
        // B stage: direct copy [k][n]
#pragma unroll
        for (int i = 0; i < 2; i++) {
            int idx = tid + i * 256;
            int kk = idx >> 5;
            int c4 = idx & 31;
            float4 v = *((const float4*)(W + (k0 + kk) * HC + n0 + 4 * c4));
            ((float4*)(Bs + kk * GP))[c4] = v;
        }
        __syncthreads();

#pragma unroll
        for (int kk = 0; kk < BKS; kk++) {
            float a[8], b[8];
#pragma unroll
            for (int i = 0; i < 8; i++) a[i] = As[kk * GP + tr * 8 + i];
#pragma unroll
            for (int j = 0; j < 8; j++) b[j] = Bs[kk * GP + tc + 16 * j];
#pragma unroll
            for (int i = 0; i < 8; i++)
#pragma unroll
                for (int j = 0; j < 8; j++) acc[i][j] += a[i] * b[j];
        }
    }

    // store h (fp16) + fused attention dots (fp32)
    float asv[8], adv[8];
#pragma unroll
    for (int j = 0; j < 8; j++) {
        asv[j] = att_src[n0 + tc + 16 * j];
        adv[j] = att_dst[n0 + tc + 16 * j];
    }
#pragma unroll
    for (int i = 0; i < 8; i++) {
        int r = m0 + tr * 8 + i;
        bool valid = (r < N_NODES);
        if (valid) {
            __half* dstp = g_hh + r * HC + n0 + tc;
#pragma unroll
            for (int j = 0; j < 8; j++) dstp[16 * j] = __float2half(acc[i][j]);
        }
        float s1 = 0.f, s2 = 0.f;
#pragma unroll
        for (int j = 0; j < 8; j++) { s1 += acc[i][j] * asv[j]; s2 += acc[i][j] * adv[j]; }
#pragma unroll
        for (int o = 8; o; o >>= 1) {
            s1 += __shfl_down_sync(0xffffffffu, s1, o, 16);
            s2 += __shfl_down_sync(0xffffffffu, s2, o, 16);
        }
        if (tc == 0 && valid) {
            g_as[r * HEADS + head] = s1;
            g_ad[r * HEADS + head] = s2;
        }
    }
}

// ------------------------- fused softmax + aggregate + GraphCON update --------
// No-max softmax (e bounded, no overflow). Block of 64 threads per node;
// thread t owns fp16 flat channels [8t..8t+7] (one 16B uint4 = 8 halves), all
// within head t/16 -> out channels 2t, 2t+1 register-local.
#define ACH 64
__global__ __launch_bounds__(64) void k_aggregate(const float* __restrict__ bias,
                                                  float* __restrict__ out, int layer) {
    __shared__ int   s_src[ACH];
    __shared__ float s_ex[ACH * 4];
    __shared__ float4 s_den[2];

    int n = blockIdx.x;
    int t = threadIdx.x;                 // 64
    int hd = t >> 4;                     // head of channels 8t..8t+7
    int wid = t >> 5, lane = t & 31;
    int st = g_off[n], en = g_off[n + 1];
    float4 ad4 = ((const float4*)g_ad)[n];
    const uint4* h16 = (const uint4*)g_hh;   // 8 halves per uint4

    float4 denp = make_float4(0.f, 0.f, 0.f, 0.f);
    float a0 = 0.f, a1 = 0.f, a2 = 0.f, a3 = 0.f;
    float a4 = 0.f, a5 = 0.f, a6 = 0.f, a7 = 0.f;

    for (int c0 = st; c0 < en; c0 += ACH) {
        int cl = en - c0; if (cl > ACH) cl = ACH;
        // phase A: exp(leakyrelu(a_s + a_d)) for this chunk's edges
        if (t < cl) {
            int s = g_csr_src[c0 + t];
            float4 as4 = ((const float4*)g_as)[s];
            float e0 = as4.x + ad4.x, e1 = as4.y + ad4.y;
            float e2 = as4.z + ad4.z, e3 = as4.w + ad4.w;
            e0 = e0 > 0.f ? e0 : e0 * NEG_SLOPE;
            e1 = e1 > 0.f ? e1 : e1 * NEG_SLOPE;
            e2 = e2 > 0.f ? e2 : e2 * NEG_SLOPE;
            e3 = e3 > 0.f ? e3 : e3 * NEG_SLOPE;
            float x0 = __expf(e0), x1 = __expf(e1), x2 = __expf(e2), x3 = __expf(e3);
            s_src[t] = s;
            ((float4*)s_ex)[t] = make_float4(x0, x1, x2, x3);
            denp.x += x0; denp.y += x1; denp.z += x2; denp.w += x3;
        }
        __syncthreads();
        // phase B: gather-accumulate fp16 rows
        int j = 0;
        for (; j + 4 <= cl; j += 4) {
            int s0 = s_src[j], s1 = s_src[j + 1], s2 = s_src[j + 2], s3 = s_src[j + 3];
            float e0 = s_ex[(j    ) * 4 + hd], e1 = s_ex[(j + 1) * 4 + hd];
            float e2 = s_ex[(j + 2) * 4 + hd], e3 = s_ex[(j + 3) * 4 + hd];
            uint4 u0 = h16[s0 * 64 + t], u1 = h16[s1 * 64 + t];
            uint4 u2 = h16[s2 * 64 + t], u3 = h16[s3 * 64 + t];
#define ACCUM(u, e) { \
            float2 p0 = __half22float2(*(const __half2*)&u.x); \
            float2 p1 = __half22float2(*(const __half2*)&u.y); \
            float2 p2 = __half22float2(*(const __half2*)&u.z); \
            float2 p3 = __half22float2(*(const __half2*)&u.w); \
            a0 += e * p0.x; a1 += e * p0.y; a2 += e * p1.x; a3 += e * p1.y; \
            a4 += e * p2.x; a5 += e * p2.y; a6 += e * p3.x; a7 += e * p3.y; }
            ACCUM(u0, e0) ACCUM(u1, e1) ACCUM(u2, e2) ACCUM(u3, e3)
        }
        for (; j < cl; j++) {
            int s = s_src[j];
            float e = s_ex[j * 4 + hd];
            uint4 u = h16[s * 64 + t];
            ACCUM(u, e)
        }
#undef ACCUM
        __syncthreads();
    }

    // reduce den across 64 threads
#pragma unroll
    for (int o = 16; o; o >>= 1) {
        denp.x += __shfl_xor_sync(0xffffffffu, denp.x, o);
        denp.y += __shfl_xor_sync(0xffffffffu, denp.y, o);
        denp.z += __shfl_xor_sync(0xffffffffu, denp.z, o);
        denp.w += __shfl_xor_sync(0xffffffffu, denp.w, o);
    }
    if (lane == 0) s_den[wid] = denp;
    __syncthreads();
    float4 d0 = s_den[0], d1 = s_den[1];
    float dens[4] = {d0.x + d1.x, d0.y + d1.y, d0.z + d1.z, d0.w + d1.w};
    float inv = 1.0f / dens[hd];

    const float4* b4p = (const float4*)(bias + 8 * t);
    float4 b0 = b4p[0], b1 = b4p[1];
    float g0 = a0 * inv + b0.x, g1 = a1 * inv + b0.y;
    float g2 = a2 * inv + b0.z, g3 = a3 * inv + b0.w;
    float g4 = a4 * inv + b1.x, g5 = a5 * inv + b1.y;
    float g6 = a6 * inv + b1.z, g7 = a7 * inv + b1.w;
    g0 = g0 > 0.f ? g0 : (expf(g0) - 1.f);
    g1 = g1 > 0.f ? g1 : (expf(g1) - 1.f);
    g2 = g2 > 0.f ? g2 : (expf(g2) - 1.f);
    g3 = g3 > 0.f ? g3 : (expf(g3) - 1.f);
    g4 = g4 > 0.f ? g4 : (expf(g4) - 1.f);
    g5 = g5 > 0.f ? g5 : (expf(g5) - 1.f);
    g6 = g6 > 0.f ? g6 : (expf(g6) - 1.f);
    g7 = g7 > 0.f ? g7 : (expf(g7) - 1.f);
    // out channels 2t (flat 8t..8t+3) and 2t+1 (flat 8t+4..8t+7)
    float aggA = 0.25f * (g0 + g1 + g2 + g3);
    float aggB = 0.25f * (g4 + g5 + g6 + g7);

    float2 xv = *((const float2*)(g_X + n * NHID + 2 * t));
    float2 yv = *((const float2*)(g_Y + n * NHID + 2 * t));
    float y2a = yv.x + DT * (aggA - ALPHA * yv.x - GAMMA * xv.x);
    float y2b = yv.y + DT * (aggB - ALPHA * yv.y - GAMMA * xv.y);
    float x2a = xv.x + DT * y2a;
    float x2b = xv.y + DT * y2b;
    *((float2*)(g_X + n * NHID + 2 * t)) = make_float2(x2a, x2b);
    *((float2*)(g_Y + n * NHID + 2 * t)) = make_float2(y2a, y2b);
    float* xo = out + XALL_OFF + n * LSTRIDE + (layer + 1) * NHID + 2 * t;
    float* yo = out + YALL_OFF + n * LSTRIDE + (layer + 1) * NHID + 2 * t;
    *((float2*)xo) = make_float2(x2a, x2b);
    *((float2*)yo) = make_float2(y2a, y2b);
}

// ------------------------- output projection ----------------------------------
__global__ void k_outproj(const float* __restrict__ Wr, const float* __restrict__ br,
                          float* __restrict__ out) {
    __shared__ float xs[NHID];
    int n = blockIdx.x;
    int t = threadIdx.x;                 // 128
    xs[t] = g_X[n * NHID + t];
    __syncthreads();
    if (t < NCLASS) {
        const float* w = Wr + t * NHID;
        float acc = 0.f;
#pragma unroll 8
        for (int k = 0; k < NHID; k++) acc += xs[k] * w[k];
        out[OUT_OFF + n * NCLASS + t] = acc + br[t];
    }
}

// ------------------------- launch ---------------------------------------------
extern "C" void kernel_launch(void* const* d_in, const int* in_sizes, int n_in,
                              void* d_out, int out_size) {
    const float* x       = (const float*)d_in[0];
    const int*   src     = (const int*)d_in[1];
    const int*   dst     = (const int*)d_in[2];
    const float* W       = (const float*)d_in[3];
    const float* att_src = (const float*)d_in[4];
    const float* att_dst = (const float*)d_in[5];
    const float* bias    = (const float*)d_in[6];
    const float* Wr      = (const float*)d_in[7];
    const float* br      = (const float*)d_in[8];
    float* out = (float*)d_out;

    int *deg_p, *cur_p;
    cudaGetSymbolAddress((void**)&deg_p, g_deg);
    cudaGetSymbolAddress((void**)&cur_p, g_cursor);

    // ---- build CSR by destination (once per call) ----
    k_zero_int2<<<(N_NODES + 255) / 256, 256>>>(deg_p, cur_p, N_NODES);
    k_count_deg<<<(ETOT + 255) / 256, 256>>>(dst);
    k_scan<<<1, 1024>>>();
    k_scatter<<<(ETOT + 255) / 256, 256>>>(src, dst);

    // ---- init state ----
    k_init<<<N_NODES, NHID>>>(x, out);

    dim3 ggrid(HC / GBN, (N_NODES + GBM - 1) / GBM);   // (4, 157)
    for (int l = 0; l < NLAYERS; l++) {
        k_gemm<<<ggrid, 256>>>(W, att_src, att_dst);
        k_aggregate<<<N_NODES, 64>>>(bias, out, l);
    }
    k_outproj<<<N_NODES, 128>>>(Wr, br, out);
}

// round 7
// speedup vs baseline: 1.8536x; 1.0326x over previous
#include <cuda_runtime.h>
#include <cuda_fp16.h>
#include <math.h>

#define N_NODES 20000
#define NHID 128
#define HEADS 4
#define HC (HEADS * NHID)          // 512
#define E_EDGES 320000
#define ETOT (E_EDGES + N_NODES)   // 340000
#define NLAYERS 4
#define NCLASS 40
#define NEG_SLOPE 0.2f
#define DT 1.0f
#define ALPHA 1.0f
#define GAMMA 1.0f

// d_out layout: [out (N*NCLASS)] [X_all (N*(L+1)*C)] [Y_all (N*(L+1)*C)]
#define OUT_OFF   0
#define XALL_OFF  (N_NODES * NCLASS)
#define YALL_OFF  (XALL_OFF + N_NODES * (NLAYERS + 1) * NHID)
#define LSTRIDE   ((NLAYERS + 1) * NHID)

// ------------------------- device scratch (no allocs allowed) ----------------
__device__ __half g_hh[N_NODES * HC];        // fp16 messages
__device__ float g_X[N_NODES * NHID];
__device__ float g_Y[N_NODES * NHID];
__device__ float g_Xhi[N_NODES * NHID];      // tf32-split X (GEMM A input)
__device__ float g_Xlo[N_NODES * NHID];
__device__ float g_Whi[NHID * HC];           // tf32-split W (split once/call)
__device__ float g_Wlo[NHID * HC];
__device__ float g_as[N_NODES * HEADS];
__device__ float g_ad[N_NODES * HEADS];
__device__ int   g_deg[N_NODES];
__device__ int   g_cursor[N_NODES];
__device__ int   g_off[N_NODES + 1];
__device__ int   g_csr_src[ETOT];

__device__ __forceinline__ void cvt_split(float x, float& hi, float& lo) {
    unsigned h, l;
    asm("cvt.rna.tf32.f32 %0, %1;" : "=r"(h) : "f"(x));
    hi = __uint_as_float(h);
    float r = x - hi;
    asm("cvt.rna.tf32.f32 %0, %1;" : "=r"(l) : "f"(r));
    lo = __uint_as_float(l);
}

__device__ __forceinline__ void mma_tf32(float* c, const unsigned* a, const unsigned* b) {
    asm volatile(
        "mma.sync.aligned.m16n8k8.row.col.f32.tf32.tf32.f32 "
        "{%0,%1,%2,%3}, {%4,%5,%6,%7}, {%8,%9}, {%0,%1,%2,%3};\n"
        : "+f"(c[0]), "+f"(c[1]), "+f"(c[2]), "+f"(c[3])
        : "r"(a[0]), "r"(a[1]), "r"(a[2]), "r"(a[3]), "r"(b[0]), "r"(b[1]));
}

// ------------------------- setup kernels -------------------------------------
__global__ void k_zero_int2(int* a, int* b, int n) {
    int i = blockIdx.x * blockDim.x + threadIdx.x;
    if (i < n) { a[i] = 0; b[i] = 0; }
}

__global__ void k_count_deg(const int* __restrict__ dst) {
    int e = blockIdx.x * blockDim.x + threadIdx.x;
    if (e >= ETOT) return;
    int d = (e < E_EDGES) ? dst[e] : (e - E_EDGES);
    atomicAdd(&g_deg[d], 1);
}

__global__ void k_scan() {
    __shared__ int s[1024];
    const int CH = (N_NODES + 1023) / 1024;
    int tid = threadIdx.x;
    int base = tid * CH;
    int sum = 0;
    for (int i = 0; i < CH; i++) {
        int idx = base + i;
        if (idx < N_NODES) sum += g_deg[idx];
    }
    s[tid] = sum;
    __syncthreads();
    for (int d = 1; d < 1024; d <<= 1) {
        int v = (tid >= d) ? s[tid - d] : 0;
        __syncthreads();
        s[tid] += v;
        __syncthreads();
    }
    int run = (tid == 0) ? 0 : s[tid - 1];
    for (int i = 0; i < CH; i++) {
        int idx = base + i;
        if (idx < N_NODES) { g_off[idx] = run; run += g_deg[idx]; }
    }
    if (tid == 1023) g_off[N_NODES] = run;
}

__global__ void k_scatter(const int* __restrict__ src, const int* __restrict__ dst) {
    int e = blockIdx.x * blockDim.x + threadIdx.x;
    if (e >= ETOT) return;
    int d, s;
    if (e < E_EDGES) { d = dst[e]; s = src[e]; }
    else { d = e - E_EDGES; s = d; }
    int pos = g_off[d] + atomicAdd(&g_cursor[d], 1);
    g_csr_src[pos] = s;
}

// split W once per call
__global__ void k_splitW(const float* __restrict__ W) {
    int i = blockIdx.x * blockDim.x + threadIdx.x;   // 0..65535
    float hi, lo;
    cvt_split(W[i], hi, lo);
    g_Whi[i] = hi;
    g_Wlo[i] = lo;
}

// init state (+ split X) + write layer-0 slices of X_all / Y_all
__global__ void k_init(const float* __restrict__ x, float* __restrict__ out) {
    int n = blockIdx.x;
    int t = threadIdx.x;
    float v = x[n * NHID + t];
    g_X[n * NHID + t] = v;
    g_Y[n * NHID + t] = v;
    float hi, lo;
    cvt_split(v, hi, lo);
    g_Xhi[n * NHID + t] = hi;
    g_Xlo[n * NHID + t] = lo;
    out[XALL_OFF + n * LSTRIDE + t] = v;
    out[YALL_OFF + n * LSTRIDE + t] = v;
}

// ------------------------- 3xTF32 tensor-core GEMM + fused attention ----------
// C[20000 x 512] = X[20000 x 128] @ W[128 x 512]. Tiles 128x128, BK=32.
// smem ~71.7 KB -> 2 CTAs/SM. A [m][k] pitch 36 (frag bank = 4g+q: conflict-
// free); B [k][n] pitch 136 (frag bank = 8q+g: conflict-free). hi/lo tiles are
// pure copies of presplit g_Xhi/lo, g_Whi/lo. Attention dots from fp32 accs.
#define GBM 128
#define GBN 128
#define BK  32
#define AP  36
#define BP  136
#define A_T (128 * AP)                 // 4608 floats per A buffer
#define B_T (BK * BP)                  // 4352 floats per B buffer
#define GEMM_SMEM ((2 * A_T + 2 * B_T) * 4)   // 71680 B

__global__ __launch_bounds__(256) void k_gemm(const float* __restrict__ att_src,
                                              const float* __restrict__ att_dst) {
    extern __shared__ float sm[];
    float* Ahi = sm;
    float* Alo = Ahi + A_T;
    float* Bhi = Alo + A_T;
    float* Blo = Bhi + B_T;

    int tid = threadIdx.x;
    int m0 = blockIdx.y * GBM;
    int n0 = blockIdx.x * GBN;          // = head * NHID
    int head = blockIdx.x;
    int warp = tid >> 5, lane = tid & 31;
    int g = lane >> 2, q = lane & 3;
    int wm = (warp >> 1) * 32;          // warp tile 32(m) x 64(n)
    int wn = (warp & 1) * 64;

    float acc[2][8][4];
#pragma unroll
    for (int mi = 0; mi < 2; mi++)
#pragma unroll
        for (int ni = 0; ni < 8; ni++)
#pragma unroll
            for (int j = 0; j < 4; j++) acc[mi][ni][j] = 0.f;

    const float4* Xhi4 = (const float4*)g_Xhi;
    const float4* Xlo4 = (const float4*)g_Xlo;
    const float4* Whi4 = (const float4*)g_Whi;
    const float4* Wlo4 = (const float4*)g_Wlo;

    for (int st = 0; st < 4; st++) {
        __syncthreads();
        // A stage: 128 rows x 8 float4 (32 k) per buffer
#pragma unroll
        for (int i = 0; i < 4; i++) {
            int idx = tid + i * 256;        // 0..1023
            int r = idx >> 3, c4 = idx & 7;
            float4 vh = make_float4(0.f, 0.f, 0.f, 0.f);
            float4 vl = vh;
            if (m0 + r < N_NODES) {
                int gidx = (m0 + r) * 32 + st * 8 + c4;
                vh = Xhi4[gidx];
                vl = Xlo4[gidx];
            }
            ((float4*)(Ahi + r * AP))[c4] = vh;
            ((float4*)(Alo + r * AP))[c4] = vl;
        }
        // B stage: 32 k-rows x 32 float4 per buffer
#pragma unroll
        for (int i = 0; i < 4; i++) {
            int idx = tid + i * 256;
            int kk = idx >> 5, c4 = idx & 31;
            int gidx = (st * 32 + kk) * (HC / 4) + (n0 >> 2) + c4;
            ((float4*)(Bhi + kk * BP))[c4] = Whi4[gidx];
            ((float4*)(Blo + kk * BP))[c4] = Wlo4[gidx];
        }
        __syncthreads();

#pragma unroll
        for (int ks = 0; ks < 4; ks++) {
            int k0 = ks * 8;
            unsigned ah[2][4], al[2][4];
#pragma unroll
            for (int mi = 0; mi < 2; mi++) {
                int r = wm + mi * 16 + g;
                ah[mi][0] = __float_as_uint(Ahi[r * AP + k0 + q]);
                ah[mi][1] = __float_as_uint(Ahi[(r + 8) * AP + k0 + q]);
                ah[mi][2] = __float_as_uint(Ahi[r * AP + k0 + 4 + q]);
                ah[mi][3] = __float_as_uint(Ahi[(r + 8) * AP + k0 + 4 + q]);
                al[mi][0] = __float_as_uint(Alo[r * AP + k0 + q]);
                al[mi][1] = __float_as_uint(Alo[(r + 8) * AP + k0 + q]);
                al[mi][2] = __float_as_uint(Alo[r * AP + k0 + 4 + q]);
                al[mi][3] = __float_as_uint(Alo[(r + 8) * AP + k0 + 4 + q]);
            }
#pragma unroll
            for (int ni = 0; ni < 8; ni++) {
                int c = wn + ni * 8 + g;
                unsigned bh[2], bl[2];
                bh[0] = __float_as_uint(Bhi[(k0 + q) * BP + c]);
                bh[1] = __float_as_uint(Bhi[(k0 + 4 + q) * BP + c]);
                bl[0] = __float_as_uint(Blo[(k0 + q) * BP + c]);
                bl[1] = __float_as_uint(Blo[(k0 + 4 + q) * BP + c]);
#pragma unroll
                for (int mi = 0; mi < 2; mi++) {
                    mma_tf32(acc[mi][ni], ah[mi], bh);
                    mma_tf32(acc[mi][ni], ah[mi], bl);
                    mma_tf32(acc[mi][ni], al[mi], bh);
                }
            }
        }
    }

    __syncthreads();                    // mainloop done; B buffers reusable
    float* sAs = Bhi;                   // [2][128]
    float* sAd = Bhi + 256;

    // attention partials over this thread's 16 columns, per owned row
    float attS[16], attD[16];
#pragma unroll
    for (int ni = 0; ni < 8; ni++) {
        int c = n0 + wn + ni * 8 + 2 * q;
        attS[2 * ni] = att_src[c];     attS[2 * ni + 1] = att_src[c + 1];
        attD[2 * ni] = att_dst[c];     attD[2 * ni + 1] = att_dst[c + 1];
    }
#pragma unroll
    for (int mi = 0; mi < 2; mi++) {
        float s1a = 0.f, s2a = 0.f, s1b = 0.f, s2b = 0.f;
#pragma unroll
        for (int ni = 0; ni < 8; ni++) {
            s1a += acc[mi][ni][0] * attS[2 * ni] + acc[mi][ni][1] * attS[2 * ni + 1];
            s2a += acc[mi][ni][0] * attD[2 * ni] + acc[mi][ni][1] * attD[2 * ni + 1];
            s1b += acc[mi][ni][2] * attS[2 * ni] + acc[mi][ni][3] * attS[2 * ni + 1];
            s2b += acc[mi][ni][2] * attD[2 * ni] + acc[mi][ni][3] * attD[2 * ni + 1];
        }
#pragma unroll
        for (int o = 2; o; o >>= 1) {
            s1a += __shfl_down_sync(0xffffffffu, s1a, o, 4);
            s2a += __shfl_down_sync(0xffffffffu, s2a, o, 4);
            s1b += __shfl_down_sync(0xffffffffu, s1b, o, 4);
            s2b += __shfl_down_sync(0xffffffffu, s2b, o, 4);
        }
        if (q == 0) {
            int half = warp & 1;
            int rA = wm + mi * 16 + g;
            sAs[half * 128 + rA] = s1a;      sAd[half * 128 + rA] = s2a;
            sAs[half * 128 + rA + 8] = s1b;  sAd[half * 128 + rA + 8] = s2b;
        }
    }
    __syncthreads();
    if (tid < 128) {
        int r = m0 + tid;
        if (r < N_NODES) {
            g_as[r * HEADS + head] = sAs[tid] + sAs[128 + tid];
            g_ad[r * HEADS + head] = sAd[tid] + sAd[128 + tid];
        }
    }

    // store h as fp16 (half2 per mma-tile column pair)
#pragma unroll
    for (int mi = 0; mi < 2; mi++) {
        int r = m0 + wm + mi * 16 + g;
#pragma unroll
        for (int ni = 0; ni < 8; ni++) {
            int c = n0 + wn + ni * 8 + 2 * q;
            if (r < N_NODES)
                *((__half2*)(g_hh + r * HC + c)) = __floats2half2_rn(acc[mi][ni][0], acc[mi][ni][1]);
            if (r + 8 < N_NODES)
                *((__half2*)(g_hh + (r + 8) * HC + c)) = __floats2half2_rn(acc[mi][ni][2], acc[mi][ni][3]);
        }
    }
}

// ------------------------- fused softmax + aggregate + GraphCON update --------
// 64 threads/node; thread t owns fp16 flat channels [8t..8t+7] (head t/16).
// Edge loop unrolled x8 for MLP.
#define ACH 64
__global__ __launch_bounds__(64) void k_aggregate(const float* __restrict__ bias,
                                                  float* __restrict__ out, int layer) {
    __shared__ int   s_src[ACH];
    __shared__ float s_ex[ACH * 4];
    __shared__ float4 s_den[2];

    int n = blockIdx.x;
    int t = threadIdx.x;
    int hd = t >> 4;
    int wid = t >> 5, lane = t & 31;
    int st = g_off[n], en = g_off[n + 1];
    float4 ad4 = ((const float4*)g_ad)[n];
    const uint4* h16 = (const uint4*)g_hh;

    float4 denp = make_float4(0.f, 0.f, 0.f, 0.f);
    float a0 = 0.f, a1 = 0.f, a2 = 0.f, a3 = 0.f;
    float a4 = 0.f, a5 = 0.f, a6 = 0.f, a7 = 0.f;

#define ACCUM(u, e) { \
    float2 p0 = __half22float2(*(const __half2*)&u.x); \
    float2 p1 = __half22float2(*(const __half2*)&u.y); \
    float2 p2 = __half22float2(*(const __half2*)&u.z); \
    float2 p3 = __half22float2(*(const __half2*)&u.w); \
    a0 += e * p0.x; a1 += e * p0.y; a2 += e * p1.x; a3 += e * p1.y; \
    a4 += e * p2.x; a5 += e * p2.y; a6 += e * p3.x; a7 += e * p3.y; }

    for (int c0 = st; c0 < en; c0 += ACH) {
        int cl = en - c0; if (cl > ACH) cl = ACH;
        if (t < cl) {
            int s = g_csr_src[c0 + t];
            float4 as4 = ((const float4*)g_as)[s];
            float e0 = as4.x + ad4.x, e1 = as4.y + ad4.y;
            float e2 = as4.z + ad4.z, e3 = as4.w + ad4.w;
            e0 = e0 > 0.f ? e0 : e0 * NEG_SLOPE;
            e1 = e1 > 0.f ? e1 : e1 * NEG_SLOPE;
            e2 = e2 > 0.f ? e2 : e2 * NEG_SLOPE;
            e3 = e3 > 0.f ? e3 : e3 * NEG_SLOPE;
            float x0 = __expf(e0), x1 = __expf(e1), x2 = __expf(e2), x3 = __expf(e3);
            s_src[t] = s;
            ((float4*)s_ex)[t] = make_float4(x0, x1, x2, x3);
            denp.x += x0; denp.y += x1; denp.z += x2; denp.w += x3;
        }
        __syncthreads();
        int j = 0;
        for (; j + 8 <= cl; j += 8) {
            int ss[8]; float ee[8]; uint4 uu[8];
#pragma unroll
            for (int u = 0; u < 8; u++) {
                ss[u] = s_src[j + u];
                ee[u] = s_ex[(j + u) * 4 + hd];
            }
#pragma unroll
            for (int u = 0; u < 8; u++) uu[u] = h16[ss[u] * 64 + t];
#pragma unroll
            for (int u = 0; u < 8; u++) ACCUM(uu[u], ee[u])
        }
        for (; j < cl; j++) {
            int s = s_src[j];
            float e = s_ex[j * 4 + hd];
            uint4 u = h16[s * 64 + t];
            ACCUM(u, e)
        }
        __syncthreads();
    }
#undef ACCUM

#pragma unroll
    for (int o = 16; o; o >>= 1) {
        denp.x += __shfl_xor_sync(0xffffffffu, denp.x, o);
        denp.y += __shfl_xor_sync(0xffffffffu, denp.y, o);
        denp.z += __shfl_xor_sync(0xffffffffu, denp.z, o);
        denp.w += __shfl_xor_sync(0xffffffffu, denp.w, o);
    }
    if (lane == 0) s_den[wid] = denp;
    __syncthreads();
    float4 d0 = s_den[0], d1 = s_den[1];
    float dens[4] = {d0.x + d1.x, d0.y + d1.y, d0.z + d1.z, d0.w + d1.w};
    float inv = 1.0f / dens[hd];

    const float4* b4p = (const float4*)(bias + 8 * t);
    float4 b0 = b4p[0], b1 = b4p[1];
    float g0 = a0 * inv + b0.x, g1 = a1 * inv + b0.y;
    float g2 = a2 * inv + b0.z, g3 = a3 * inv + b0.w;
    float g4 = a4 * inv + b1.x, g5 = a5 * inv + b1.y;
    float g6 = a6 * inv + b1.z, g7 = a7 * inv + b1.w;
    g0 = g0 > 0.f ? g0 : (expf(g0) - 1.f);
    g1 = g1 > 0.f ? g1 : (expf(g1) - 1.f);
    g2 = g2 > 0.f ? g2 : (expf(g2) - 1.f);
    g3 = g3 > 0.f ? g3 : (expf(g3) - 1.f);
    g4 = g4 > 0.f ? g4 : (expf(g4) - 1.f);
    g5 = g5 > 0.f ? g5 : (expf(g5) - 1.f);
    g6 = g6 > 0.f ? g6 : (expf(g6) - 1.f);
    g7 = g7 > 0.f ? g7 : (expf(g7) - 1.f);
    float aggA = 0.25f * (g0 + g1 + g2 + g3);
    float aggB = 0.25f * (g4 + g5 + g6 + g7);

    float2 xv = *((const float2*)(g_X + n * NHID + 2 * t));
    float2 yv = *((const float2*)(g_Y + n * NHID + 2 * t));
    float y2a = yv.x + DT * (aggA - ALPHA * yv.x - GAMMA * xv.x);
    float y2b = yv.y + DT * (aggB - ALPHA * yv.y - GAMMA * xv.y);
    float x2a = xv.x + DT * y2a;
    float x2b = xv.y + DT * y2b;
    *((float2*)(g_X + n * NHID + 2 * t)) = make_float2(x2a, x2b);
    *((float2*)(g_Y + n * NHID + 2 * t)) = make_float2(y2a, y2b);
    // presplit X for next layer's GEMM
    float hiA, loA, hiB, loB;
    cvt_split(x2a, hiA, loA);
    cvt_split(x2b, hiB, loB);
    *((float2*)(g_Xhi + n * NHID + 2 * t)) = make_float2(hiA, hiB);
    *((float2*)(g_Xlo + n * NHID + 2 * t)) = make_float2(loA, loB);

    float* xo = out + XALL_OFF + n * LSTRIDE + (layer + 1) * NHID + 2 * t;
    float* yo = out + YALL_OFF + n * LSTRIDE + (layer + 1) * NHID + 2 * t;
    *((float2*)xo) = make_float2(x2a, x2b);
    *((float2*)yo) = make_float2(y2a, y2b);
}

// ------------------------- output projection ----------------------------------
__global__ void k_outproj(const float* __restrict__ Wr, const float* __restrict__ br,
                          float* __restrict__ out) {
    __shared__ float xs[NHID];
    int n = blockIdx.x;
    int t = threadIdx.x;
    xs[t] = g_X[n * NHID + t];
    __syncthreads();
    if (t < NCLASS) {
        const float* w = Wr + t * NHID;
        float acc = 0.f;
#pragma unroll 8
        for (int k = 0; k < NHID; k++) acc += xs[k] * w[k];
        out[OUT_OFF + n * NCLASS + t] = acc + br[t];
    }
}

// ------------------------- launch ---------------------------------------------
extern "C" void kernel_launch(void* const* d_in, const int* in_sizes, int n_in,
                              void* d_out, int out_size) {
    const float* x       = (const float*)d_in[0];
    const int*   src     = (const int*)d_in[1];
    const int*   dst     = (const int*)d_in[2];
    const float* W       = (const float*)d_in[3];
    const float* att_src = (const float*)d_in[4];
    const float* att_dst = (const float*)d_in[5];
    const float* bias    = (const float*)d_in[6];
    const float* Wr      = (const float*)d_in[7];
    const float* br      = (const float*)d_in[8];
    float* out = (float*)d_out;

    cudaFuncSetAttribute(k_gemm, cudaFuncAttributeMaxDynamicSharedMemorySize, GEMM_SMEM);

    int *deg_p, *cur_p;
    cudaGetSymbolAddress((void**)&deg_p, g_deg);
    cudaGetSymbolAddress((void**)&cur_p, g_cursor);

    // ---- build CSR by destination + split W (once per call) ----
    k_zero_int2<<<(N_NODES + 255) / 256, 256>>>(deg_p, cur_p, N_NODES);
    k_count_deg<<<(ETOT + 255) / 256, 256>>>(dst);
    k_scan<<<1, 1024>>>();
    k_scatter<<<(ETOT + 255) / 256, 256>>>(src, dst);
    k_splitW<<<(NHID * HC) / 256, 256>>>(W);

    // ---- init state ----
    k_init<<<N_NODES, NHID>>>(x, out);

    dim3 ggrid(HC / GBN, (N_NODES + GBM - 1) / GBM);   // (4, 157)
    for (int l = 0; l < NLAYERS; l++) {
        k_gemm<<<ggrid, 256, GEMM_SMEM>>>(att_src, att_dst);
        k_aggregate<<<N_NODES, 64>>>(bias, out, l);
    }
    k_outproj<<<N_NODES, 128>>>(Wr, br, out);
}